// round 12
// baseline (speedup 1.0000x reference)
#include <cuda_runtime.h>

#define NB 4
#define NA 160000
#define NG 64
#define NBLK 74              // K1 blocks per batch image (grid 74*4 = 296 = 2*148: one wave @occ2)
#define K1_STRIDE (NBLK*256) // 18944
#define NBLK9 33             // blocks 0..32: 9 anchors/thread; 33..73: 8  (33*9+41*8=625)

// Scratch (__device__ globals; no init required by construction)
// g_best[i]: bits[0:31) = float bits of best (rounded) IoU; bit 31 = lowq flag (K2).
__device__ unsigned g_best[NB * NA];
__device__ float    g_blockmax[NB * NBLK * NG]; // per-block per-gt rounded col max

__device__ __forceinline__ float box_area(float4 b) {
    return __fmul_rn(__fadd_rn(b.z, -b.x), __fadd_rn(b.w, -b.y));
}

// Reference-exact (fully clamped) IoU. Used by K2 / K3 for ALL equality and
// argmax tests. Same _rn sequence + __fdividef everywhere => bit-identical
// for a given (anchor, gt) wherever it is evaluated.
__device__ __forceinline__ float iou_pair(float4 a, float areaA, float4 g, float areaG) {
    float ltx = fmaxf(g.x, a.x);
    float lty = fmaxf(g.y, a.y);
    float rbx = fminf(g.z, a.z);
    float rby = fminf(g.w, a.w);
    float w = fmaxf(__fadd_rn(rbx, -ltx), 0.0f);
    float h = fmaxf(__fadd_rn(rby, -lty), 0.0f);
    float inter = __fmul_rn(w, h);
    float denom = __fadd_rn(__fadd_rn(areaA, areaG), -inter);
    return __fdividef(inter, denom);   // inter==0 -> exactly 0; denom>0 always
}

// Fast tracking IoU for K1: h left unclamped (saves one FMNMX). w >= 0, so
// whenever the true overlap is empty this returns q <= 0, which the >=0-
// initialized fmax trackers ignore (reference clamped value there is 0).
// Whenever the true overlap is positive, max(x,0)==x bit-exactly, so the
// value is bit-identical to iou_pair. Hence every value RETAINED by a
// tracker (best / cmax, floored at 0) equals the clamped reference value.
__device__ __forceinline__ float iou_fast(float4 a, float areaA, float4 g, float areaG) {
    float ltx = fmaxf(g.x, a.x);
    float lty = fmaxf(g.y, a.y);
    float rbx = fminf(g.z, a.z);
    float rby = fminf(g.w, a.w);
    float w = fmaxf(__fadd_rn(rbx, -ltx), 0.0f);
    float h = __fadd_rn(rby, -lty);            // unclamped
    float inter = __fmul_rn(w, h);             // sign(h) when w>0; 0 when w==0
    float denom = __fadd_rn(__fadd_rn(areaA, areaG), -inter);
    return __fdividef(inter, denom);
}

__device__ __forceinline__ unsigned warp_max_u32(unsigned v) {
    unsigned r;
    asm("redux.sync.max.u32 %0, %1, 0xffffffff;" : "=r"(r) : "r"(v));
    return r;
}

// ---------------------------------------------------------------------------
// K1: single full IoU pass; 7 alu ops/pair (6 corner/clamp + 2 trackers - 1).
// Produces per-anchor best (floored at 0 == reference) and per-block per-gt
// column max (floored at 0 == reference).
// ---------------------------------------------------------------------------
template <int KA>
__device__ __forceinline__ void k1_body(
    const float4* __restrict__ anchors, int b, int blk, int tid,
    const float4* sg, const float* sga, unsigned int* smax)
{
    const int a0 = blk * 256 + tid;
    const int lane = tid & 31;

    float4 an[KA]; float areaA[KA]; float best[KA];
#pragma unroll
    for (int k = 0; k < KA; ++k) {
        int a = a0 + k * K1_STRIDE;
        an[k] = anchors[b * NA + a];
        areaA[k] = box_area(an[k]);
        best[k] = 0.0f;                // floor 0: negatives (empty overlap) ignored
    }

    float gown[2] = {0.0f, 0.0f};      // rounded tile col-max for g = lane, lane+32

#pragma unroll 2
    for (int g = 0; g < NG; ++g) {
        float4 gb = sg[g];
        float  ag = sga[g];

        float cmax = 0.0f;             // floor 0
#pragma unroll
        for (int k = 0; k < KA; ++k) {
            float q = iou_fast(an[k], areaA[k], gb, ag);
            cmax = fmaxf(cmax, q);
            best[k] = fmaxf(best[k], q);
        }

        unsigned wm = warp_max_u32(__float_as_uint(cmax));   // vals >= 0: uint order ok
        if (lane == (g & 31))
            gown[g >> 5] = __uint_as_float(wm);
    }

#pragma unroll
    for (int k = 0; k < KA; ++k) {
        int a = a0 + k * K1_STRIDE;
        g_best[b * NA + a] = __float_as_uint(best[k]);   // bit31 clear (best >= 0)
    }

    atomicMax(&smax[lane],      __float_as_uint(gown[0]));
    atomicMax(&smax[lane + 32], __float_as_uint(gown[1]));
}

__global__ __launch_bounds__(256, 2)
void k_main(const float4* __restrict__ anchors, const float4* __restrict__ gts)
{
    const int b = blockIdx.y;
    const int blk = blockIdx.x;
    const int tid = threadIdx.x;

    __shared__ float4 sg[NG];
    __shared__ float  sga[NG];
    __shared__ unsigned int smax[NG];

    if (tid < NG) {
        float4 g = gts[b * NG + tid];
        sg[tid] = g;
        sga[tid] = box_area(g);
        smax[tid] = 0u;
    }
    __syncthreads();

    if (blk < NBLK9) k1_body<9>(anchors, b, blk, tid, sg, sga, smax);
    else             k1_body<8>(anchors, b, blk, tid, sg, sga, smax);

    __syncthreads();
    if (tid < NG)
        g_blockmax[(b * NBLK + blk) * NG + tid] = __uint_as_float(smax[tid]);
}

// ---------------------------------------------------------------------------
// K2: sparse low-quality pass. One block per (gt,batch) column: reduce the 74
// block maxima to the column max, rescan only blocks achieving it with the
// CLAMPED iou, set bit 31 of g_best on rounded equality (exact reference
// semantics, including the degenerate shigh==0 case).
// ---------------------------------------------------------------------------
__global__ __launch_bounds__(256)
void k_lowq(const float4* __restrict__ anchors, const float4* __restrict__ gts)
{
    const int g = blockIdx.x;
    const int b = blockIdx.y;
    const int tid = threadIdx.x;

    __shared__ float red[256];
    __shared__ int   list[NBLK];
    __shared__ int   cnt;

    if (tid == 0) cnt = 0;
    float m = (tid < NBLK) ? g_blockmax[(b * NBLK + tid) * NG + g] : 0.0f;
    red[tid] = m;
    __syncthreads();
#pragma unroll
    for (int s = 128; s; s >>= 1) {
        if (tid < s) red[tid] = fmaxf(red[tid], red[tid + s]);
        __syncthreads();
    }
    const float shigh = red[0];

    if (tid < NBLK && m == shigh) {
        int i = atomicAdd(&cnt, 1);
        list[i] = tid;
    }
    __syncthreads();

    const int n = cnt;
    float4 gb = gts[b * NG + g];
    float  ag = box_area(gb);

    for (int i = 0; i < n; ++i) {
        int blk = list[i];
#pragma unroll
        for (int k = 0; k < 9; ++k) {       // covers both the 9- and 8-anchor blocks
            int a = blk * 256 + k * K1_STRIDE + tid;
            if (a < NA) {
                float4 an = anchors[b * NA + a];
                float v = iou_pair(an, box_area(an), gb, ag);
                if (v == shigh)
                    atomicOr(&g_best[b * NA + a], 0x80000000u);
            }
        }
    }
}

// ---------------------------------------------------------------------------
// K3: label + matched-box writer; sparse argmax recovery only for positive
// anchors (lowq flag or best >= 0.7), using the CLAMPED iou: first g with
// q == best == reference first-occurrence argmax (incl. all-zero rows).
// ---------------------------------------------------------------------------
__global__ __launch_bounds__(256)
void k_label(const float4* __restrict__ anchors,
             const float4* __restrict__ gts, const float* __restrict__ scores,
             const int* __restrict__ confs,
             float* __restrict__ outL, float4* __restrict__ outB)
{
    const int b = blockIdx.y;
    const int tid = threadIdx.x;

    __shared__ float4 sg[NG];
    __shared__ float  sga[NG];
    __shared__ float  ss[NG];
    __shared__ int    sc[NG];
    if (tid < NG) {
        float4 g = gts[b * NG + tid];
        sg[tid] = g;
        sga[tid] = box_area(g);
        ss[tid] = scores[b * NG + tid];
        sc[tid] = confs[b * NG + tid];
    }
    __syncthreads();

    const int a = blockIdx.x * 256 + tid;   // NA = 625*256 exactly
    const int idx = b * NA + a;

    unsigned bb = g_best[idx];
    bool lowq = (bb & 0x80000000u) != 0u;
    float best = __uint_as_float(bb & 0x7FFFFFFFu);
    bool pos = lowq || (best >= 0.7f);

    int bestg = 0;
    if (pos) {
        float4 an = anchors[idx];
        float areaA = box_area(an);
#pragma unroll 4
        for (int g = 0; g < NG; ++g) {
            if (iou_pair(an, areaA, sg[g], sga[g]) == best) { bestg = g; break; }
        }
    }

    // Matcher: positive -> bestg ; else <0.3 -> -1 ; else (0.3..0.7) -> -2.
    int midx = pos ? bestg : (best >= 0.3f ? -2 : -1);
    int cl = pos ? bestg : 0;

    float s = ss[cl];
    int c = sc[cl];
    float label = (midx == -1) ? 0.0f
                : (midx == -2) ? -1.0f
                : ((s < 1.0f || c == 0) ? -1.0f : 1.0f);

    outL[idx] = label;
    outB[idx] = sg[cl];
}

extern "C" void kernel_launch(void* const* d_in, const int* in_sizes, int n_in,
                              void* d_out, int out_size) {
    (void)in_sizes; (void)n_in; (void)out_size;
    const float4* anchors = (const float4*)d_in[0];   // [B, A, 4] f32
    const float4* gts     = (const float4*)d_in[1];   // [B, G, 4] f32
    const float*  scores  = (const float*)d_in[2];    // [B, G] f32
    const int*    confs   = (const int*)d_in[3];      // [B, G] i32

    float*  outL = (float*)d_out;                      // labels [B, A]
    float4* outB = (float4*)((float*)d_out + NB * NA); // matched boxes [B, A, 4]

    k_main <<<dim3(NBLK, NB), 256>>>(anchors, gts);
    k_lowq <<<dim3(NG,   NB), 256>>>(anchors, gts);
    k_label<<<dim3(NA / 256, NB), 256>>>(anchors, gts, scores, confs, outL, outB);
}

// round 13
// speedup vs baseline: 1.5693x; 1.5693x over previous
#include <cuda_runtime.h>

#define NB 4
#define NA 160000
#define NG 64
#define NBLK 74              // blocks per batch image: 74*4 = 296 = 148 SMs * occ2
#define GRID (NBLK * NB)     // 296, exactly one resident wave (deadlock-free spin)
#define K1_STRIDE (NBLK*256) // 18944
#define NBLK9 33             // blocks 0..32: 9 anchors/thread; 33..73: 8 (33*9+41*8=625)
#define NTILE 2500           // label tiles of 256 anchors (NB * 625)

// Scratch (__device__ globals; zero-init at module load)
// g_best[i]: bits[0:31) = float bits of best (rounded) IoU; bit 31 = lowq flag.
__device__ unsigned g_best[NB * NA];
__device__ float    g_blockmax[NB * NBLK * NG];
__device__ unsigned g_bar;   // monotone grid-barrier counter (never reset; gen arithmetic)

// Reference-exact IoU: same _rn sequence + __fdividef at every evaluation site
// => bit-identical per (anchor,gt) across all phases. Equality tests
// (q == colmax for lowq, q == best for argmax) therefore implement exactly
// the reference's  mq == highest_per_gt  and first-occurrence  jnp.argmax.
__device__ __forceinline__ float box_area(float4 b) {
    return __fmul_rn(__fadd_rn(b.z, -b.x), __fadd_rn(b.w, -b.y));
}

__device__ __forceinline__ float iou_pair(float4 a, float areaA, float4 g, float areaG) {
    float ltx = fmaxf(g.x, a.x);
    float lty = fmaxf(g.y, a.y);
    float rbx = fminf(g.z, a.z);
    float rby = fminf(g.w, a.w);
    float w = fmaxf(__fadd_rn(rbx, -ltx), 0.0f);
    float h = fmaxf(__fadd_rn(rby, -lty), 0.0f);
    float inter = __fmul_rn(w, h);
    float denom = __fadd_rn(__fadd_rn(areaA, areaG), -inter);
    return __fdividef(inter, denom);   // inter==0 -> exactly 0; denom>0 always
}

__device__ __forceinline__ unsigned warp_max_u32(unsigned v) {
    unsigned r;
    asm("redux.sync.max.u32 %0, %1, 0xffffffff;" : "=r"(r) : "r"(v));
    return r;
}

// Grid-wide barrier: monotone counter + generation target. All GRID CTAs are
// co-resident (one wave), so spinning is safe. Works unchanged across graph
// replays (counter keeps growing; target derives from the arrival value).
__device__ __forceinline__ void grid_barrier() {
    __syncthreads();
    if (threadIdx.x == 0) {
        __threadfence();
        unsigned old = atomicAdd(&g_bar, 1u);
        unsigned target = (old / GRID + 1u) * GRID;
        while (*(volatile unsigned*)&g_bar < target) { }
        __threadfence();
    }
    __syncthreads();
}

// ---------------------------------------------------------------------------
// Phase A body (R9-proven): full IoU pass, two fmax trackers per pair.
// ---------------------------------------------------------------------------
template <int KA>
__device__ __forceinline__ void k1_body(
    const float4* __restrict__ anchors, int b, int blk, int tid,
    const float4* sg, const float* sga, unsigned int* smax)
{
    const int a0 = blk * 256 + tid;
    const int lane = tid & 31;

    float4 an[KA]; float areaA[KA]; float best[KA];
#pragma unroll
    for (int k = 0; k < KA; ++k) {
        int a = a0 + k * K1_STRIDE;
        an[k] = anchors[b * NA + a];
        areaA[k] = box_area(an[k]);
        best[k] = 0.0f;                // q >= 0: fmax chain == true max
    }

    float gown[2] = {0.0f, 0.0f};

#pragma unroll 2
    for (int g = 0; g < NG; ++g) {
        float4 gb = sg[g];
        float  ag = sga[g];

        float cmax = 0.0f;
#pragma unroll
        for (int k = 0; k < KA; ++k) {
            float q = iou_pair(an[k], areaA[k], gb, ag);
            cmax = fmaxf(cmax, q);
            best[k] = fmaxf(best[k], q);
        }

        unsigned wm = warp_max_u32(__float_as_uint(cmax));   // IoU>=0: uint order ok
        if (lane == (g & 31))
            gown[g >> 5] = __uint_as_float(wm);
    }

#pragma unroll
    for (int k = 0; k < KA; ++k) {
        int a = a0 + k * K1_STRIDE;
        g_best[b * NA + a] = __float_as_uint(best[k]);   // bit31 clear (best >= 0)
    }

    atomicMax(&smax[lane],      __float_as_uint(gown[0]));
    atomicMax(&smax[lane + 32], __float_as_uint(gown[1]));
}

// ---------------------------------------------------------------------------
// Fused persistent kernel: Phase A (full pass) -> barrier -> Phase B (sparse
// lowq, 256 columns) -> barrier -> Phase C (labels, 2500 tiles over 296 CTAs).
// ---------------------------------------------------------------------------
__global__ __launch_bounds__(256, 2)
void k_fused(const float4* __restrict__ anchors, const float4* __restrict__ gts,
             const float* __restrict__ scores, const int* __restrict__ confs,
             float* __restrict__ outL, float4* __restrict__ outB)
{
    const int cta = blockIdx.x;        // 0..295
    const int tid = threadIdx.x;

    __shared__ float4 sg[NG];
    __shared__ float  sga[NG];
    __shared__ unsigned int smax[NG];
    __shared__ float  red[256];
    __shared__ int    list[NBLK];
    __shared__ int    cnt;
    // Phase C tables: all 4 batches
    __shared__ float4 sgAll[NB * NG];
    __shared__ float  sgaAll[NB * NG];
    __shared__ float  ssAll[NB * NG];
    __shared__ int    scAll[NB * NG];

    // ---------------- Phase A ----------------
    {
        const int b   = cta / NBLK;
        const int blk = cta % NBLK;

        if (tid < NG) {
            float4 g = gts[b * NG + tid];
            sg[tid] = g;
            sga[tid] = box_area(g);
            smax[tid] = 0u;
        }
        __syncthreads();

        if (blk < NBLK9) k1_body<9>(anchors, b, blk, tid, sg, sga, smax);
        else             k1_body<8>(anchors, b, blk, tid, sg, sga, smax);

        __syncthreads();
        if (tid < NG)
            g_blockmax[(b * NBLK + blk) * NG + tid] = __uint_as_float(smax[tid]);
    }

    grid_barrier();

    // ---------------- Phase B: sparse low-quality (columns 0..255) ----------
    if (cta < NB * NG) {
        const int g = cta & (NG - 1);
        const int b = cta >> 6;

        if (tid == 0) cnt = 0;
        float m = (tid < NBLK) ? g_blockmax[(b * NBLK + tid) * NG + g] : 0.0f;
        red[tid] = m;
        __syncthreads();
#pragma unroll
        for (int s = 128; s; s >>= 1) {
            if (tid < s) red[tid] = fmaxf(red[tid], red[tid + s]);
            __syncthreads();
        }
        const float shigh = red[0];

        if (tid < NBLK && m == shigh) {
            int i = atomicAdd(&cnt, 1);
            list[i] = tid;
        }
        __syncthreads();

        const int n = cnt;
        float4 gb = gts[b * NG + g];
        float  ag = box_area(gb);

        for (int i = 0; i < n; ++i) {
            int blk = list[i];
#pragma unroll
            for (int k = 0; k < 9; ++k) {   // covers both 9- and 8-anchor blocks
                int a = blk * 256 + k * K1_STRIDE + tid;
                if (a < NA) {
                    float4 an = anchors[b * NA + a];
                    float v = iou_pair(an, box_area(an), gb, ag);
                    if (v == shigh)
                        atomicOr(&g_best[b * NA + a], 0x80000000u);
                }
            }
        }
    }

    // Stage phase-C tables (independent of phase B's g_best writes)
    if (tid < NB * NG) {   // 256 == NB*NG
        float4 g = gts[tid];
        sgAll[tid] = g;
        sgaAll[tid] = box_area(g);
        ssAll[tid] = scores[tid];
        scAll[tid] = confs[tid];
    }

    grid_barrier();

    // ---------------- Phase C: labels + matched boxes ----------------------
    for (int t = cta; t < NTILE; t += GRID) {
        const int b = t / 625;
        const int a = (t % 625) * 256 + tid;
        const int idx = b * NA + a;
        const int gbase = b * NG;

        unsigned bb = g_best[idx];
        bool lowq = (bb & 0x80000000u) != 0u;
        float best = __uint_as_float(bb & 0x7FFFFFFFu);
        bool pos = lowq || (best >= 0.7f);

        int bestg = 0;
        if (pos) {
            float4 an = anchors[idx];
            float areaA = box_area(an);
#pragma unroll 4
            for (int g = 0; g < NG; ++g) {
                if (iou_pair(an, areaA, sgAll[gbase + g], sgaAll[gbase + g]) == best) {
                    bestg = g; break;   // first occurrence == jnp.argmax
                }
            }
        }

        // Matcher: positive -> bestg ; else <0.3 -> -1 ; else (0.3..0.7) -> -2.
        int midx = pos ? bestg : (best >= 0.3f ? -2 : -1);
        int cl = pos ? bestg : 0;

        float s = ssAll[gbase + cl];
        int c = scAll[gbase + cl];
        float label = (midx == -1) ? 0.0f
                    : (midx == -2) ? -1.0f
                    : ((s < 1.0f || c == 0) ? -1.0f : 1.0f);

        outL[idx] = label;
        outB[idx] = sgAll[gbase + cl];
    }
}

extern "C" void kernel_launch(void* const* d_in, const int* in_sizes, int n_in,
                              void* d_out, int out_size) {
    (void)in_sizes; (void)n_in; (void)out_size;
    const float4* anchors = (const float4*)d_in[0];   // [B, A, 4] f32
    const float4* gts     = (const float4*)d_in[1];   // [B, G, 4] f32
    const float*  scores  = (const float*)d_in[2];    // [B, G] f32
    const int*    confs   = (const int*)d_in[3];      // [B, G] i32

    float*  outL = (float*)d_out;                      // labels [B, A]
    float4* outB = (float4*)((float*)d_out + NB * NA); // matched boxes [B, A, 4]

    k_fused<<<GRID, 256>>>(anchors, gts, scores, confs, outL, outB);
}

// round 14
// speedup vs baseline: 1.6033x; 1.0217x over previous
#include <cuda_runtime.h>

#define NB 4
#define NA 160000
#define NG 64
#define NBLK 74              // K1 blocks per batch image (grid 74*4 = 296 = 2*148: one wave @occ2)
#define K1_STRIDE (NBLK*256) // 18944
#define NBLK9 33             // blocks 0..32: 9 anchors/thread; 33..73: 8  (33*9+41*8=625)

// Scratch: per-block per-gt rounded column max. Plain stores each launch.
__device__ float g_blockmax[NB * NBLK * NG];

// Reference-exact IoU: same _rn sequence + __fdividef at every evaluation site
// => bit-identical per (anchor,gt) across both kernels. Equality tests
// (q == shigh for lowq, q == best / strict > for argmax) therefore implement
// exactly the reference's  mq == highest_per_gt  and first-occurrence argmax.
__device__ __forceinline__ float box_area(float4 b) {
    return __fmul_rn(__fadd_rn(b.z, -b.x), __fadd_rn(b.w, -b.y));
}

__device__ __forceinline__ float iou_pair(float4 a, float areaA, float4 g, float areaG) {
    float ltx = fmaxf(g.x, a.x);
    float lty = fmaxf(g.y, a.y);
    float rbx = fminf(g.z, a.z);
    float rby = fminf(g.w, a.w);
    float w = fmaxf(__fadd_rn(rbx, -ltx), 0.0f);
    float h = fmaxf(__fadd_rn(rby, -lty), 0.0f);
    float inter = __fmul_rn(w, h);
    float denom = __fadd_rn(__fadd_rn(areaA, areaG), -inter);
    return __fdividef(inter, denom);   // inter==0 -> exactly 0; denom>0 always
}

__device__ __forceinline__ unsigned warp_max_u32(unsigned v) {
    unsigned r;
    asm("redux.sync.max.u32 %0, %1, 0xffffffff;" : "=r"(r) : "r"(v));
    return r;
}

// ---------------------------------------------------------------------------
// K1: full IoU pass (hot loop identical to the 32.2us R9 version) + direct
// label/box emission for the non-lowq world. Positive anchors (best >= 0.7)
// take a rare cold branch to recover the first-occurrence argmax.
// ---------------------------------------------------------------------------
template <int KA>
__device__ __forceinline__ void k1_body(
    const float4* __restrict__ anchors, int b, int blk, int tid,
    const float4* sg, const float* sga, const float* ss, const int* sc,
    unsigned int* smax, float* __restrict__ outL, float4* __restrict__ outB)
{
    const int a0 = blk * 256 + tid;
    const int lane = tid & 31;

    float4 an[KA]; float areaA[KA]; float best[KA];
#pragma unroll
    for (int k = 0; k < KA; ++k) {
        int a = a0 + k * K1_STRIDE;
        an[k] = anchors[b * NA + a];
        areaA[k] = box_area(an[k]);
        best[k] = 0.0f;                // q >= 0: fmax chain == true max
    }

    float gown[2] = {0.0f, 0.0f};

#pragma unroll 2
    for (int g = 0; g < NG; ++g) {
        float4 gb = sg[g];
        float  ag = sga[g];

        float cmax = 0.0f;
#pragma unroll
        for (int k = 0; k < KA; ++k) {
            float q = iou_pair(an[k], areaA[k], gb, ag);
            cmax = fmaxf(cmax, q);
            best[k] = fmaxf(best[k], q);
        }

        unsigned wm = warp_max_u32(__float_as_uint(cmax));   // IoU>=0: uint order ok
        if (lane == (g & 31))
            gown[g >> 5] = __uint_as_float(wm);
    }

    // ----- epilogue: emit labels/boxes assuming no low-quality override -----
#pragma unroll
    for (int k = 0; k < KA; ++k) {
        int a = a0 + k * K1_STRIDE;
        float bv = best[k];
        bool pos = (bv >= 0.7f);

        int bestg = 0;
        if (pos) {                      // rare cold path: recover argmax
            float4 an_ = an[k]; float aa = areaA[k];
            for (int g = 0; g < NG; ++g) {
                if (iou_pair(an_, aa, sg[g], sga[g]) == bv) { bestg = g; break; }
            }
        }

        int cl = pos ? bestg : 0;
        float s = ss[cl];
        int c = sc[cl];
        // pos: min(1,s) then forced -1 if s<1 or conf==0  => (s<1||c==0)?-1:1
        // non-pos: best>=0.3 -> BETWEEN(-1) ; else BELOW(0)
        float label = pos ? ((s < 1.0f || c == 0) ? -1.0f : 1.0f)
                          : (bv >= 0.3f ? -1.0f : 0.0f);

        outL[b * NA + a] = label;
        outB[b * NA + a] = sg[cl];
    }

    atomicMax(&smax[lane],      __float_as_uint(gown[0]));
    atomicMax(&smax[lane + 32], __float_as_uint(gown[1]));
}

__global__ __launch_bounds__(256, 2)
void k_main(const float4* __restrict__ anchors, const float4* __restrict__ gts,
            const float* __restrict__ scores, const int* __restrict__ confs,
            float* __restrict__ outL, float4* __restrict__ outB)
{
    const int b = blockIdx.y;
    const int blk = blockIdx.x;
    const int tid = threadIdx.x;

    __shared__ float4 sg[NG];
    __shared__ float  sga[NG];
    __shared__ float  ss[NG];
    __shared__ int    sc[NG];
    __shared__ unsigned int smax[NG];

    if (tid < NG) {
        float4 g = gts[b * NG + tid];
        sg[tid] = g;
        sga[tid] = box_area(g);
        ss[tid] = scores[b * NG + tid];
        sc[tid] = confs[b * NG + tid];
        smax[tid] = 0u;
    }
    __syncthreads();

    if (blk < NBLK9) k1_body<9>(anchors, b, blk, tid, sg, sga, ss, sc, smax, outL, outB);
    else             k1_body<8>(anchors, b, blk, tid, sg, sga, ss, sc, smax, outL, outB);

    __syncthreads();
    if (tid < NG)
        g_blockmax[(b * NBLK + blk) * NG + tid] = __uint_as_float(smax[tid]);
}

// ---------------------------------------------------------------------------
// K2: low-quality FIXUP. One block per (gt,batch) column: reduce the 74 block
// maxima to shigh, rescan only winner blocks; every anchor with q == shigh is
// low-quality -> recompute its row argmax (first occurrence) and OVERWRITE
// its label and matched box with the positive-path values. Racing duplicate
// writes (anchor tied on several columns) store identical values.
// ---------------------------------------------------------------------------
__global__ __launch_bounds__(256)
void k_fixup(const float4* __restrict__ anchors, const float4* __restrict__ gts,
             const float* __restrict__ scores, const int* __restrict__ confs,
             float* __restrict__ outL, float4* __restrict__ outB)
{
    const int g = blockIdx.x;
    const int b = blockIdx.y;
    const int tid = threadIdx.x;

    __shared__ float4 sg[NG];
    __shared__ float  sga[NG];
    __shared__ float  ss[NG];
    __shared__ int    sc[NG];
    __shared__ float  red[256];
    __shared__ int    list[NBLK];
    __shared__ int    cnt;

    if (tid < NG) {
        float4 gb_ = gts[b * NG + tid];
        sg[tid] = gb_;
        sga[tid] = box_area(gb_);
        ss[tid] = scores[b * NG + tid];
        sc[tid] = confs[b * NG + tid];
    }
    if (tid == 0) cnt = 0;
    float m = (tid < NBLK) ? g_blockmax[(b * NBLK + tid) * NG + g] : 0.0f;
    red[tid] = m;
    __syncthreads();
#pragma unroll
    for (int s = 128; s; s >>= 1) {
        if (tid < s) red[tid] = fmaxf(red[tid], red[tid + s]);
        __syncthreads();
    }
    const float shigh = red[0];

    if (tid < NBLK && m == shigh) {
        int i = atomicAdd(&cnt, 1);
        list[i] = tid;
    }
    __syncthreads();

    const int n = cnt;
    const float4 gb = sg[g];
    const float  ag = sga[g];

    for (int i = 0; i < n; ++i) {
        int blk = list[i];
#pragma unroll
        for (int k = 0; k < 9; ++k) {       // covers both 9- and 8-anchor blocks
            int a = blk * 256 + k * K1_STRIDE + tid;
            if (a < NA) {
                float4 an = anchors[b * NA + a];
                float areaA = box_area(an);
                float v = iou_pair(an, areaA, gb, ag);
                if (v == shigh) {           // low-quality anchor: full fixup
                    float bv = -1.0f; int bestg = 0;
                    for (int gg = 0; gg < NG; ++gg) {
                        float q = iou_pair(an, areaA, sg[gg], sga[gg]);
                        if (q > bv) { bv = q; bestg = gg; }  // strict >: first occurrence
                    }
                    float s = ss[bestg];
                    int c = sc[bestg];
                    float label = (s < 1.0f || c == 0) ? -1.0f : 1.0f;
                    outL[b * NA + a] = label;
                    outB[b * NA + a] = sg[bestg];
                }
            }
        }
    }
}

extern "C" void kernel_launch(void* const* d_in, const int* in_sizes, int n_in,
                              void* d_out, int out_size) {
    (void)in_sizes; (void)n_in; (void)out_size;
    const float4* anchors = (const float4*)d_in[0];   // [B, A, 4] f32
    const float4* gts     = (const float4*)d_in[1];   // [B, G, 4] f32
    const float*  scores  = (const float*)d_in[2];    // [B, G] f32
    const int*    confs   = (const int*)d_in[3];      // [B, G] i32

    float*  outL = (float*)d_out;                      // labels [B, A]
    float4* outB = (float4*)((float*)d_out + NB * NA); // matched boxes [B, A, 4]

    k_main <<<dim3(NBLK, NB), 256>>>(anchors, gts, scores, confs, outL, outB);
    k_fixup<<<dim3(NG,   NB), 256>>>(anchors, gts, scores, confs, outL, outB);
}